// round 10
// baseline (speedup 1.0000x reference)
#include <cuda_runtime.h>
#include <cuda_bf16.h>

#define NB 64
#define NT 512
#define ND 1024
#define BPB 16  // batches per block

// streaming (evict-first) float4 store
__device__ __forceinline__ void stcs4(float4* p, float4 v) {
    asm volatile("st.global.cs.v4.f32 [%0], {%1,%2,%3,%4};"
                 :: "l"(p), "f"(v.x), "f"(v.y), "f"(v.z), "f"(v.w) : "memory");
}

// ---------------------------------------------------------------------------
// Warp-cooperative local chain_pos: since c(t) is nondecreasing, the
// reference's cummax baseline equals c at the LATEST reset j* <= t, so
// chain_pos = count of rel>0 in [j*, t). Backward ballot search finds j*
// (expected ~1 window of 32), then a short popc count.
// ---------------------------------------------------------------------------
__device__ __forceinline__ int warp_chain_pos(const int* __restrict__ rel_row,
                                              int t, int lane) {
    // find latest j* <= t with rel[j]==0 && rel[j-1]>0 (no reset at j=0)
    int jstar = 0;
    int hi = t;
    while (true) {
        const int idx = hi - 31 + lane;          // window [hi-31, hi]
        const int relv = (idx >= 1) ? rel_row[idx] : 1;
        const int relp = (idx >= 1) ? rel_row[idx - 1] : 0;
        const bool reset = (idx >= 1) && (relv == 0) && (relp > 0);
        const unsigned bal = __ballot_sync(0xFFFFFFFFu, reset);
        if (bal) { jstar = hi - 31 + (31 - __clz(bal)); break; }
        hi -= 32;
        if (hi < 1) { jstar = 0; break; }
    }
    // count rel>0 over [jstar, t)
    int cnt = 0;
    for (int base = jstar; base < t; base += 32) {
        const int k = base + lane;
        const bool p = (k < t) && (rel_row[k] > 0);
        cnt += __popc(__ballot_sync(0xFFFFFFFFu, p));
    }
    return cnt;  // identical on all lanes
}

// ---------------------------------------------------------------------------
// Single fused kernel. Grid (NT, NB/BPB) = (512, 4), 256 thr/block (8 warps).
// Preamble: issue the 5 table-row loads; warps 0..7 each compute (cp, role)
// for 2 batches locally (no inter-block dependency); then the R2-style
// inner loop: chain gather (L2-hot) + FFMA + streaming STG.128.
// ---------------------------------------------------------------------------
__global__ __launch_bounds__(256) void gpe_fused_kernel(
    const int* __restrict__ input_ids,
    const int* __restrict__ rel_ids,
    const float* __restrict__ seq_table,
    const float* __restrict__ chain_table,
    const float* __restrict__ depth_table,
    const float* __restrict__ role_table,
    float* __restrict__ out) {

    const int t = blockIdx.x;
    const int b0 = blockIdx.y * BPB;
    const int tid = threadIdx.x;
    const int lane = tid & 31;
    const int w = tid >> 5;
    const int d = tid * 4;

    __shared__ int spk[BPB];

    // ---- issue long-latency table loads first ----
    const float4 s4 = *(const float4*)(seq_table + (size_t)t * ND + d);
    const float4 dp = *(const float4*)(depth_table + d);  // depth row 0 always
    float4 r0 = *(const float4*)(role_table + 0 * ND + d);
    float4 r2 = *(const float4*)(role_table + 2 * ND + d);
    float4 r3 = *(const float4*)(role_table + 3 * ND + d);

    // ---- per-warp local scan: warp w handles batches 2w and 2w+1 ----
#pragma unroll
    for (int s = 0; s < 2; s++) {
        const int bl = 2 * w + s;              // local batch 0..15
        const int b = b0 + bl;
        const int* rel_row = rel_ids + b * NT;
        const int cp = warp_chain_pos(rel_row, t, lane);
        if (lane == 0) {
            const int rel_t = rel_row[t];
            const int id_t = input_ids[b * NT + t];
            const int role = (id_t <= 4) ? 3 : ((rel_t == 0) ? 2 : 0);
            spk[bl] = cp | (role << 16);
        }
    }

    float4 base;
    base.x = s4.x + 0.3f * dp.x;
    base.y = s4.y + 0.3f * dp.y;
    base.z = s4.z + 0.3f * dp.z;
    base.w = s4.w + 0.3f * dp.w;
    r0.x *= 0.2f; r0.y *= 0.2f; r0.z *= 0.2f; r0.w *= 0.2f;
    r2.x *= 0.2f; r2.y *= 0.2f; r2.z *= 0.2f; r2.w *= 0.2f;
    r3.x *= 0.2f; r3.y *= 0.2f; r3.z *= 0.2f; r3.w *= 0.2f;

    __syncthreads();

#pragma unroll 8
    for (int i = 0; i < BPB; i++) {
        const int pk = spk[i];
        const int cp = pk & 0xFFFF;
        const int role = pk >> 16;

        const float4 c4 = *(const float4*)(chain_table + (size_t)cp * ND + d);
        const float4 r4 = (role == 3) ? r3 : ((role == 2) ? r2 : r0);

        float4 o;
        o.x = base.x + 0.5f * c4.x + r4.x;
        o.y = base.y + 0.5f * c4.y + r4.y;
        o.z = base.z + 0.5f * c4.z + r4.z;
        o.w = base.w + 0.5f * c4.w + r4.w;

        stcs4((float4*)(out + ((size_t)(b0 + i) * NT + t) * ND + d), o);
    }
}

extern "C" void kernel_launch(void* const* d_in, const int* in_sizes, int n_in,
                              void* d_out, int out_size) {
    const int* input_ids   = (const int*)d_in[0];
    const int* rel_ids     = (const int*)d_in[1];
    const float* seq_table = (const float*)d_in[2];
    const float* chain_tab = (const float*)d_in[3];
    const float* depth_tab = (const float*)d_in[4];
    const float* role_tab  = (const float*)d_in[5];
    float* out = (float*)d_out;

    dim3 grid(NT, NB / BPB);
    gpe_fused_kernel<<<grid, 256>>>(input_ids, rel_ids, seq_table, chain_tab,
                                    depth_tab, role_tab, out);
}